// round 2
// baseline (speedup 1.0000x reference)
#include <cuda_runtime.h>
#include <math.h>

#define C_DIM 256
#define N_DIM 4096
#define B_DIM 2
#define HEADS 8
#define HD 32
#define BCN (B_DIM * C_DIM * N_DIM)   // 2097152

// ---------------- scratch (no allocations allowed) ----------------
__device__ float g_scale[B_DIM * C_DIM];
__device__ float g_shift[B_DIM * C_DIM];
__device__ float g_qkv[3 * BCN];       // Q,K,V each [B][C][N]
__device__ float g_attnout[BCN];       // attention output [B][C][N]

// ---------------- GroupNorm stats -> per-channel scale/shift ----------------
// grid: 16 blocks (b*8+g), 256 threads. Group data is contiguous: 32ch*4096 = 131072 floats.
__global__ __launch_bounds__(256) void gn_stats_kernel(
    const float* __restrict__ x, const float* __restrict__ gw,
    const float* __restrict__ gb, float* __restrict__ scl, float* __restrict__ shf)
{
    int bg = blockIdx.x;
    int b = bg >> 3, g = bg & 7;
    const float* p = x + (size_t)(b * C_DIM + g * 32) * N_DIM;
    float s = 0.f, s2 = 0.f;
    for (int i = threadIdx.x; i < 131072 / 4; i += 256) {
        float4 v = reinterpret_cast<const float4*>(p)[i];
        s  += v.x + v.y + v.z + v.w;
        s2 += v.x * v.x + v.y * v.y + v.z * v.z + v.w * v.w;
    }
    __shared__ float rs[256], rs2[256];
    rs[threadIdx.x] = s; rs2[threadIdx.x] = s2;
    __syncthreads();
    for (int st = 128; st; st >>= 1) {
        if (threadIdx.x < st) {
            rs[threadIdx.x]  += rs[threadIdx.x + st];
            rs2[threadIdx.x] += rs2[threadIdx.x + st];
        }
        __syncthreads();
    }
    __shared__ float mu_s, rstd_s;
    if (threadIdx.x == 0) {
        float m = rs[0] * (1.f / 131072.f);
        float var = rs2[0] * (1.f / 131072.f) - m * m;
        mu_s = m;
        rstd_s = rsqrtf(var + 1e-5f);
    }
    __syncthreads();
    if (threadIdx.x < 32) {
        int c = g * 32 + threadIdx.x;
        float sc = gw[c] * rstd_s;
        scl[b * C_DIM + c] = sc;
        shf[b * C_DIM + c] = gb[c] - mu_s * sc;
    }
}

// ---------------- generic 256-K GEMM: Y[b,o,n] = sum_c W[o,c]*(X[b,c,n]*s+t) + bias (+resid) ----
// grid: (64 n-tiles, 4 o-tiles, 2 batches); block 256; tile 64o x 64n, BK=32; 4x4 micro-tile.
__global__ __launch_bounds__(256) void gemm256_kernel(
    const float* __restrict__ W, const float* __restrict__ bias,
    const float* __restrict__ X, const float* __restrict__ scale,
    const float* __restrict__ shift, const float* __restrict__ resid,
    float* __restrict__ Y)
{
    const int n0 = blockIdx.x * 64;
    const int o0 = blockIdx.y * 64;
    const int b  = blockIdx.z;
    const int tid = threadIdx.x;
    const int nt = tid & 15, ot = tid >> 4;

    __shared__ float As[32][65];                      // [k][o], transposed store (conflict-free)
    __shared__ __align__(16) float Bs[32][68];        // [k][n], float4-aligned rows

    const size_t xbase = (size_t)b * C_DIM * N_DIM;
    float acc[4][4] = {};

    for (int k0 = 0; k0 < C_DIM; k0 += 32) {
        // A tile: W[o0+o][k0+c], 64x32, transposed into As[c][o]
        #pragma unroll
        for (int r = 0; r < 2; r++) {
            int idx = tid + r * 256;
            int o = idx >> 3, c4 = (idx & 7) << 2;
            float4 w4 = *reinterpret_cast<const float4*>(W + (size_t)(o0 + o) * C_DIM + k0 + c4);
            As[c4 + 0][o] = w4.x; As[c4 + 1][o] = w4.y;
            As[c4 + 2][o] = w4.z; As[c4 + 3][o] = w4.w;
        }
        // B tile: X[b][k0+c][n0+n], 32x64, apply groupnorm scale/shift on the fly
        #pragma unroll
        for (int r = 0; r < 2; r++) {
            int idx = tid + r * 256;
            int c = idx >> 4, n4 = (idx & 15) << 2;
            float4 v = *reinterpret_cast<const float4*>(X + xbase + (size_t)(k0 + c) * N_DIM + n0 + n4);
            if (scale != nullptr) {
                float s = scale[b * C_DIM + k0 + c];
                float t = shift[b * C_DIM + k0 + c];
                v.x = fmaf(v.x, s, t); v.y = fmaf(v.y, s, t);
                v.z = fmaf(v.z, s, t); v.w = fmaf(v.w, s, t);
            }
            *reinterpret_cast<float4*>(&Bs[c][n4]) = v;
        }
        __syncthreads();
        #pragma unroll
        for (int k = 0; k < 32; k++) {
            float a0 = As[k][(ot << 2) + 0];
            float a1 = As[k][(ot << 2) + 1];
            float a2 = As[k][(ot << 2) + 2];
            float a3 = As[k][(ot << 2) + 3];
            float4 bv = *reinterpret_cast<const float4*>(&Bs[k][nt << 2]);
            acc[0][0] += a0 * bv.x; acc[0][1] += a0 * bv.y; acc[0][2] += a0 * bv.z; acc[0][3] += a0 * bv.w;
            acc[1][0] += a1 * bv.x; acc[1][1] += a1 * bv.y; acc[1][2] += a1 * bv.z; acc[1][3] += a1 * bv.w;
            acc[2][0] += a2 * bv.x; acc[2][1] += a2 * bv.y; acc[2][2] += a2 * bv.z; acc[2][3] += a2 * bv.w;
            acc[3][0] += a3 * bv.x; acc[3][1] += a3 * bv.y; acc[3][2] += a3 * bv.z; acc[3][3] += a3 * bv.w;
        }
        __syncthreads();
    }
    #pragma unroll
    for (int i = 0; i < 4; i++) {
        int o = o0 + (ot << 2) + i;
        float bo = bias[o];
        size_t off = xbase + (size_t)o * N_DIM + n0 + (nt << 2);
        float4 v;
        v.x = acc[i][0] + bo; v.y = acc[i][1] + bo;
        v.z = acc[i][2] + bo; v.w = acc[i][3] + bo;
        if (resid != nullptr) {
            float4 rr = *reinterpret_cast<const float4*>(resid + off);
            v.x += rr.x; v.y += rr.y; v.z += rr.z; v.w += rr.w;
        }
        *reinterpret_cast<float4*>(Y + off) = v;
    }
}

// ---------------- Flash attention: 64q x 64m tiles, D=32 ----------------
// grid: (64 q-blocks, 8 heads, 2 batches); 256 threads.
__global__ __launch_bounds__(256) void flash_kernel(
    const float* __restrict__ qkv, float* __restrict__ aout)
{
    const int q0 = blockIdx.x * 64;
    const int h  = blockIdx.y;
    const int b  = blockIdx.z;
    const int tid = threadIdx.x;

    __shared__ __align__(16) float Qs[32][68];
    __shared__ __align__(16) float Ks[32][68];
    __shared__ float Vt[64][33];                 // transposed V: [m][d], conflict-free scalar reads
    __shared__ __align__(16) float Ps[64][68];   // P tile; reused as O-transpose buffer at end
    __shared__ float Ms[64], Ls[64], Corr[64], Nm[64];

    const size_t headoff = (size_t)(b * C_DIM + h * HD) * N_DIM;
    const float* Qg = qkv + headoff;
    const float* Kg = qkv + (size_t)BCN + headoff;
    const float* Vg = qkv + 2ull * BCN + headoff;

    // load Q tile, pre-scaled by 1/sqrt(32)
    const float qsc = 0.17677669529663687f;
    #pragma unroll
    for (int r = 0; r < 2; r++) {
        int idx = tid + r * 256;
        int d = idx >> 4, c4 = (idx & 15) << 2;
        float4 v = *reinterpret_cast<const float4*>(Qg + (size_t)d * N_DIM + q0 + c4);
        v.x *= qsc; v.y *= qsc; v.z *= qsc; v.w *= qsc;
        *reinterpret_cast<float4*>(&Qs[d][c4]) = v;
    }
    if (tid < 64) { Ms[tid] = -1e30f; Ls[tid] = 0.f; }

    const int mt = tid & 15, qt = tid >> 4;      // layout A: S[qt*4+i][mt*4+j]
    const int dt = tid & 7,  qt2 = tid >> 3;     // layout B: O[qt2*2+r][dt*4+k]
    const int d0 = dt << 2;
    float acc[2][4] = {};

    for (int m0 = 0; m0 < N_DIM; m0 += 64) {
        __syncthreads();
        // K tile [d][m]
        #pragma unroll
        for (int r = 0; r < 2; r++) {
            int idx = tid + r * 256;
            int d = idx >> 4, m4 = (idx & 15) << 2;
            float4 v = *reinterpret_cast<const float4*>(Kg + (size_t)d * N_DIM + m0 + m4);
            *reinterpret_cast<float4*>(&Ks[d][m4]) = v;
        }
        // V tile transposed -> Vt[m][d]
        #pragma unroll
        for (int r = 0; r < 2; r++) {
            int idx = tid + r * 256;
            int d = idx >> 4, m4 = (idx & 15) << 2;
            float4 v = *reinterpret_cast<const float4*>(Vg + (size_t)d * N_DIM + m0 + m4);
            Vt[m4 + 0][d] = v.x; Vt[m4 + 1][d] = v.y;
            Vt[m4 + 2][d] = v.z; Vt[m4 + 3][d] = v.w;
        }
        __syncthreads();

        // S = Q^T K (already scaled)
        float s[4][4] = {};
        #pragma unroll
        for (int d = 0; d < 32; d++) {
            float4 qv = *reinterpret_cast<const float4*>(&Qs[d][qt << 2]);
            float4 kv = *reinterpret_cast<const float4*>(&Ks[d][mt << 2]);
            s[0][0] += qv.x * kv.x; s[0][1] += qv.x * kv.y; s[0][2] += qv.x * kv.z; s[0][3] += qv.x * kv.w;
            s[1][0] += qv.y * kv.x; s[1][1] += qv.y * kv.y; s[1][2] += qv.y * kv.z; s[1][3] += qv.y * kv.w;
            s[2][0] += qv.z * kv.x; s[2][1] += qv.z * kv.y; s[2][2] += qv.z * kv.z; s[2][3] += qv.z * kv.w;
            s[3][0] += qv.w * kv.x; s[3][1] += qv.w * kv.y; s[3][2] += qv.w * kv.z; s[3][3] += qv.w * kv.w;
        }
        // online softmax: row max across 16 mt lanes
        #pragma unroll
        for (int i = 0; i < 4; i++) {
            float r = fmaxf(fmaxf(s[i][0], s[i][1]), fmaxf(s[i][2], s[i][3]));
            #pragma unroll
            for (int off = 8; off; off >>= 1)
                r = fmaxf(r, __shfl_xor_sync(0xffffffffu, r, off));
            if (mt == 0) {
                int q = (qt << 2) + i;
                float nm = fmaxf(Ms[q], r);
                Corr[q] = __expf(Ms[q] - nm);
                Ms[q] = nm;
                Nm[q] = nm;
            }
        }
        __syncthreads();
        // P = exp(S - nm); row sums; write P tile
        #pragma unroll
        for (int i = 0; i < 4; i++) {
            int q = (qt << 2) + i;
            float nm = Nm[q];
            float p0 = __expf(s[i][0] - nm);
            float p1 = __expf(s[i][1] - nm);
            float p2 = __expf(s[i][2] - nm);
            float p3 = __expf(s[i][3] - nm);
            float4 pv = {p0, p1, p2, p3};
            *reinterpret_cast<float4*>(&Ps[q][mt << 2]) = pv;
            float rs = (p0 + p1) + (p2 + p3);
            #pragma unroll
            for (int off = 8; off; off >>= 1)
                rs += __shfl_xor_sync(0xffffffffu, rs, off);
            if (mt == 0) Ls[q] = Ls[q] * Corr[q] + rs;
        }
        __syncthreads();
        // O = O*corr + P @ V^T
        {
            float c0 = Corr[qt2 * 2], c1 = Corr[qt2 * 2 + 1];
            #pragma unroll
            for (int k = 0; k < 4; k++) { acc[0][k] *= c0; acc[1][k] *= c1; }
            #pragma unroll 4
            for (int m = 0; m < 64; m++) {
                float p0 = Ps[qt2 * 2][m];
                float p1 = Ps[qt2 * 2 + 1][m];
                float v0 = Vt[m][d0], v1 = Vt[m][d0 + 1], v2 = Vt[m][d0 + 2], v3 = Vt[m][d0 + 3];
                acc[0][0] += p0 * v0; acc[0][1] += p0 * v1; acc[0][2] += p0 * v2; acc[0][3] += p0 * v3;
                acc[1][0] += p1 * v0; acc[1][1] += p1 * v1; acc[1][2] += p1 * v2; acc[1][3] += p1 * v3;
            }
        }
    }
    __syncthreads();
    // normalize and transpose via smem (reuse Ps as [q][d] stride 33)
    {
        float inv0 = 1.f / Ls[qt2 * 2];
        float inv1 = 1.f / Ls[qt2 * 2 + 1];
        float* Os = &Ps[0][0];
        #pragma unroll
        for (int k = 0; k < 4; k++) {
            Os[(qt2 * 2) * 33 + d0 + k]     = acc[0][k] * inv0;
            Os[(qt2 * 2 + 1) * 33 + d0 + k] = acc[1][k] * inv1;
        }
    }
    __syncthreads();
    {
        float* Os = &Ps[0][0];
        float* outp = aout + headoff;
        #pragma unroll
        for (int r = 0; r < 8; r++) {
            int idx = tid + r * 256;
            int d = idx >> 6, q = idx & 63;
            outp[(size_t)d * N_DIM + q0 + q] = Os[q * 33 + d];
        }
    }
}

// ---------------- launch ----------------
extern "C" void kernel_launch(void* const* d_in, const int* in_sizes, int n_in,
                              void* d_out, int out_size)
{
    const float* x    = (const float*)d_in[0];
    const float* gn_w = (const float*)d_in[1];
    const float* gn_b = (const float*)d_in[2];
    const float* wq   = (const float*)d_in[3];
    const float* bq   = (const float*)d_in[4];
    const float* wk   = (const float*)d_in[5];
    const float* bk   = (const float*)d_in[6];
    const float* wv   = (const float*)d_in[7];
    const float* bv   = (const float*)d_in[8];
    const float* wo   = (const float*)d_in[9];
    const float* bo   = (const float*)d_in[10];
    float* out = (float*)d_out;

    float *scl, *shf, *qkv, *attn;
    cudaGetSymbolAddress((void**)&scl,  g_scale);
    cudaGetSymbolAddress((void**)&shf,  g_shift);
    cudaGetSymbolAddress((void**)&qkv,  g_qkv);
    cudaGetSymbolAddress((void**)&attn, g_attnout);

    gn_stats_kernel<<<16, 256>>>(x, gn_w, gn_b, scl, shf);

    dim3 ggrid(64, 4, 2);
    gemm256_kernel<<<ggrid, 256>>>(wq, bq, x, scl, shf, nullptr, qkv);
    gemm256_kernel<<<ggrid, 256>>>(wk, bk, x, scl, shf, nullptr, qkv + BCN);
    gemm256_kernel<<<ggrid, 256>>>(wv, bv, x, scl, shf, nullptr, qkv + 2 * (size_t)BCN);

    dim3 fgrid(64, HEADS, B_DIM);
    flash_kernel<<<fgrid, 256>>>(qkv, attn);

    gemm256_kernel<<<ggrid, 256>>>(wo, bo, attn, nullptr, nullptr, x, out);
}

// round 7
// speedup vs baseline: 5.3611x; 5.3611x over previous
#include <cuda_runtime.h>
#include <cuda_fp16.h>
#include <cstdint>
#include <math.h>

#define C_DIM 256
#define N_DIM 4096
#define B_DIM 2
#define HEADS 8
#define BCN (B_DIM * C_DIM * N_DIM)   // 2097152

// ---------------- scratch ----------------
__device__ float g_scale[B_DIM * C_DIM];
__device__ float g_shift[B_DIM * C_DIM];
__device__ __align__(16) __half g_qnd[BCN];   // [b*8+h][n][32] fp16, pre-scaled by log2e/sqrt(32)
__device__ __align__(16) __half g_knd[BCN];   // [b*8+h][n][32] fp16
__device__ __align__(16) __half g_vdn[BCN];   // [b][c][n] fp16  (per head: [d][n])
__device__ float g_attn[BCN];                 // attention out fp32 [b][c][n]

// ---------------- helpers ----------------
__device__ __forceinline__ uint32_t smem_u32(const void* p) {
    uint32_t a;
    asm("{ .reg .u64 t; cvta.to.shared.u64 t, %1; cvt.u32.u64 %0, t; }" : "=r"(a) : "l"(p));
    return a;
}
__device__ __forceinline__ uint32_t packh(float lo, float hi) {
    uint32_t r; asm("cvt.rn.f16x2.f32 %0, %1, %2;" : "=r"(r) : "f"(hi), "f"(lo)); return r;
}
#define H2EXP(x) asm("ex2.approx.f16x2 %0, %0;" : "+r"(x))

#define CP16(dst, src) asm volatile("cp.async.cg.shared.global [%0], [%1], 16;" :: "r"(dst), "l"(src))
#define CP_COMMIT()    asm volatile("cp.async.commit_group;" ::: "memory")
#define CP_WAIT(n)     asm volatile("cp.async.wait_group %0;" :: "n"(n) : "memory")

#define LDSM4(r0, r1, r2, r3, a) \
    asm volatile("ldmatrix.sync.aligned.m8n8.x4.shared.b16 {%0,%1,%2,%3}, [%4];" \
        : "=r"(r0), "=r"(r1), "=r"(r2), "=r"(r3) : "r"(a))

#define MMA_F16(d0, d1, a0, a1, a2, a3, b0, b1, c0, c1) \
    asm volatile("mma.sync.aligned.m16n8k16.row.col.f16.f16.f16.f16 " \
        "{%0,%1},{%2,%3,%4,%5},{%6,%7},{%8,%9};" \
        : "=r"(d0), "=r"(d1) \
        : "r"(a0), "r"(a1), "r"(a2), "r"(a3), "r"(b0), "r"(b1), "r"(c0), "r"(c1))

#define MMA_F32(D, a0, a1, a2, a3, b0, b1) \
    asm volatile("mma.sync.aligned.m16n8k16.row.col.f32.f16.f16.f32 " \
        "{%0,%1,%2,%3},{%4,%5,%6,%7},{%8,%9},{%0,%1,%2,%3};" \
        : "+f"((D)[0]), "+f"((D)[1]), "+f"((D)[2]), "+f"((D)[3]) \
        : "r"(a0), "r"(a1), "r"(a2), "r"(a3), "r"(b0), "r"(b1))

// ---------------- GroupNorm stats ----------------
__global__ __launch_bounds__(256) void gn_stats_kernel(
    const float* __restrict__ x, const float* __restrict__ gw,
    const float* __restrict__ gb, float* __restrict__ scl, float* __restrict__ shf)
{
    int bg = blockIdx.x;
    int b = bg >> 3, g = bg & 7;
    const float* p = x + (size_t)(b * C_DIM + g * 32) * N_DIM;
    float s = 0.f, s2 = 0.f;
    for (int i = threadIdx.x; i < 131072 / 4; i += 256) {
        float4 v = reinterpret_cast<const float4*>(p)[i];
        s  += v.x + v.y + v.z + v.w;
        s2 += v.x * v.x + v.y * v.y + v.z * v.z + v.w * v.w;
    }
    __shared__ float rs[256], rs2[256];
    rs[threadIdx.x] = s; rs2[threadIdx.x] = s2;
    __syncthreads();
    for (int st = 128; st; st >>= 1) {
        if (threadIdx.x < st) {
            rs[threadIdx.x]  += rs[threadIdx.x + st];
            rs2[threadIdx.x] += rs2[threadIdx.x + st];
        }
        __syncthreads();
    }
    __shared__ float mu_s, rstd_s;
    if (threadIdx.x == 0) {
        float m = rs[0] * (1.f / 131072.f);
        float var = rs2[0] * (1.f / 131072.f) - m * m;
        mu_s = m;
        rstd_s = rsqrtf(var + 1e-5f);
    }
    __syncthreads();
    if (threadIdx.x < 32) {
        int c = g * 32 + threadIdx.x;
        float sc = gw[c] * rstd_s;
        scl[b * C_DIM + c] = sc;
        shf[b * C_DIM + c] = gb[c] - mu_s * sc;
    }
}

// ---------------- GEMM (64o x 64n tile) ----------------
// mode 0: fp32 acc+bias+resid -> Yf [b][o][n]
// mode 1: fp16 (acc+bias)*outscale -> Yh [(b*8 + o/32)][n][o%32]
// mode 2: fp16 acc+bias -> Yh [b][o][n]
__global__ __launch_bounds__(256) void gemm256_kernel(
    const float* __restrict__ W, const float* __restrict__ bias,
    const float* __restrict__ X, const float* __restrict__ scale,
    const float* __restrict__ shift, const float* __restrict__ resid,
    float* __restrict__ Yf, __half* __restrict__ Yh,
    int mode, float outscale)
{
    const int n0 = blockIdx.x * 64;
    const int o0 = blockIdx.y * 64;
    const int b  = blockIdx.z;
    const int tid = threadIdx.x;
    const int nt = tid & 15, ot = tid >> 4;

    __shared__ float As[32][65];
    __shared__ __align__(16) float Bs[32][68];

    const size_t xbase = (size_t)b * C_DIM * N_DIM;
    float acc[4][4] = {};

    for (int k0 = 0; k0 < C_DIM; k0 += 32) {
        #pragma unroll
        for (int r = 0; r < 2; r++) {
            int idx = tid + r * 256;
            int o = idx >> 3, c4 = (idx & 7) << 2;
            float4 w4 = *reinterpret_cast<const float4*>(W + (size_t)(o0 + o) * C_DIM + k0 + c4);
            As[c4 + 0][o] = w4.x; As[c4 + 1][o] = w4.y;
            As[c4 + 2][o] = w4.z; As[c4 + 3][o] = w4.w;
        }
        #pragma unroll
        for (int r = 0; r < 2; r++) {
            int idx = tid + r * 256;
            int c = idx >> 4, n4 = (idx & 15) << 2;
            float4 v = *reinterpret_cast<const float4*>(X + xbase + (size_t)(k0 + c) * N_DIM + n0 + n4);
            if (scale != nullptr) {
                float s = scale[b * C_DIM + k0 + c];
                float t = shift[b * C_DIM + k0 + c];
                v.x = fmaf(v.x, s, t); v.y = fmaf(v.y, s, t);
                v.z = fmaf(v.z, s, t); v.w = fmaf(v.w, s, t);
            }
            *reinterpret_cast<float4*>(&Bs[c][n4]) = v;
        }
        __syncthreads();
        #pragma unroll
        for (int k = 0; k < 32; k++) {
            float a0 = As[k][(ot << 2) + 0];
            float a1 = As[k][(ot << 2) + 1];
            float a2 = As[k][(ot << 2) + 2];
            float a3 = As[k][(ot << 2) + 3];
            float4 bv = *reinterpret_cast<const float4*>(&Bs[k][nt << 2]);
            acc[0][0] += a0 * bv.x; acc[0][1] += a0 * bv.y; acc[0][2] += a0 * bv.z; acc[0][3] += a0 * bv.w;
            acc[1][0] += a1 * bv.x; acc[1][1] += a1 * bv.y; acc[1][2] += a1 * bv.z; acc[1][3] += a1 * bv.w;
            acc[2][0] += a2 * bv.x; acc[2][1] += a2 * bv.y; acc[2][2] += a2 * bv.z; acc[2][3] += a2 * bv.w;
            acc[3][0] += a3 * bv.x; acc[3][1] += a3 * bv.y; acc[3][2] += a3 * bv.z; acc[3][3] += a3 * bv.w;
        }
        __syncthreads();
    }

    if (mode == 0) {
        #pragma unroll
        for (int i = 0; i < 4; i++) {
            int o = o0 + (ot << 2) + i;
            float bo = bias[o];
            size_t off = xbase + (size_t)o * N_DIM + n0 + (nt << 2);
            float4 v;
            v.x = acc[i][0] + bo; v.y = acc[i][1] + bo;
            v.z = acc[i][2] + bo; v.w = acc[i][3] + bo;
            float4 rr = *reinterpret_cast<const float4*>(resid + off);
            v.x += rr.x; v.y += rr.y; v.z += rr.z; v.w += rr.w;
            *reinterpret_cast<float4*>(Yf + off) = v;
        }
    } else if (mode == 1) {
        int ob = o0 + (ot << 2);
        int hh = ob >> 5, dl = ob & 31;
        float b0 = bias[ob], b1 = bias[ob + 1], b2 = bias[ob + 2], b3 = bias[ob + 3];
        __half* qp = Yh + (size_t)(b * HEADS + hh) * N_DIM * 32 + dl;
        #pragma unroll
        for (int j = 0; j < 4; j++) {
            int n = n0 + (nt << 2) + j;
            uint2 pk;
            pk.x = packh((acc[0][j] + b0) * outscale, (acc[1][j] + b1) * outscale);
            pk.y = packh((acc[2][j] + b2) * outscale, (acc[3][j] + b3) * outscale);
            *reinterpret_cast<uint2*>(qp + (size_t)n * 32) = pk;
        }
    } else {
        #pragma unroll
        for (int i = 0; i < 4; i++) {
            int o = o0 + (ot << 2) + i;
            float bo = bias[o];
            uint2 pk;
            pk.x = packh(acc[i][0] + bo, acc[i][1] + bo);
            pk.y = packh(acc[i][2] + bo, acc[i][3] + bo);
            *reinterpret_cast<uint2*>(Yh + xbase + (size_t)o * N_DIM + n0 + (nt << 2)) = pk;
        }
    }
}

// ---------------- flash attention via mma.sync fp16 ----------------
// smem layout (static, 48128 B):
//   Q:  [128 rows][80 B]   @ 0      (10240)
//   K0: [128 rows][80 B]   @ 10240  (10240)
//   K1: [128 rows][80 B]   @ 20480  (10240)
//   V0: [32 rows][272 B]   @ 30720  (8704)
//   V1: [32 rows][272 B]   @ 39424  (8704)
// O staging reuses K0/K1 region (32 x 132 fp32 = 16896 B).
#define SMQ  0
#define SMK0 10240
#define SMK1 20480
#define SMV0 30720
#define SMV1 39424

__global__ __launch_bounds__(256) void flash_mma_kernel(
    const __half* __restrict__ Qg_, const __half* __restrict__ Kg_,
    const __half* __restrict__ Vg_, float* __restrict__ aout)
{
    __shared__ __align__(16) char smem[48128];
    const int q0 = blockIdx.x * 128;
    const int h = blockIdx.y, b = blockIdx.z;
    const int tid = threadIdx.x;
    const int w = tid >> 5, lane = tid & 31;
    const uint32_t sb = smem_u32(smem);

    const int bh = b * HEADS + h;
    const __half* Qg = Qg_ + (size_t)bh * N_DIM * 32;
    const __half* Kg = Kg_ + (size_t)bh * N_DIM * 32;
    const __half* Vg = Vg_ + (size_t)(b * C_DIM + h * 32) * N_DIM;

    // load Q tile (plain)
    for (int c = tid; c < 512; c += 256) {
        int row = c >> 2, seg = c & 3;
        uint4 v = *reinterpret_cast<const uint4*>(Qg + (size_t)(q0 + row) * 32 + seg * 8);
        *reinterpret_cast<uint4*>(smem + SMQ + row * 80 + seg * 16) = v;
    }

    auto prefK = [&](int m0, uint32_t base) {
        for (int c = tid; c < 512; c += 256) {
            int row = c >> 2, seg = c & 3;
            CP16(sb + base + row * 80 + seg * 16,
                 Kg + (size_t)(m0 + row) * 32 + seg * 8);
        }
    };
    auto prefV = [&](int m0, uint32_t base) {
        for (int c = tid; c < 512; c += 256) {
            int d = c >> 4, seg = c & 15;
            CP16(sb + base + d * 272 + seg * 16,
                 Vg + (size_t)d * N_DIM + m0 + seg * 8);
        }
    };
    prefK(0, SMK0);
    prefV(0, SMV0);
    CP_COMMIT();
    __syncthreads();

    // Q a-frags (K=32 -> 2 k-steps)
    uint32_t QA[2][4];
    {
        uint32_t qaddr = sb + SMQ + (16 * w + (lane & 15)) * 80 + ((lane & 16) ? 16 : 0);
        LDSM4(QA[0][0], QA[0][1], QA[0][2], QA[0][3], qaddr);
        LDSM4(QA[1][0], QA[1][1], QA[1][2], QA[1][3], qaddr + 32);
    }

    const uint32_t rowoff_k = ((lane & 7) + ((lane & 16) ? 8 : 0)) * 80 + ((lane & 8) ? 16 : 0);
    const uint32_t rowoff_v = ((lane & 7) + ((lane & 16) ? 8 : 0)) * 272 + ((lane & 8) ? 16 : 0);
    const uint32_t bone = ((lane >> 2) == 0) ? 0x3C003C00u : 0u;  // ones in col 0

    float O[4][4] = {};
    float Osum[4] = {};

    for (int it = 0; it < 32; it++) {
        const int cur = it & 1;
        if (it + 1 < 32) {
            prefK(128 * (it + 1), cur ? SMK0 : SMK1);
            prefV(128 * (it + 1), cur ? SMV0 : SMV1);
            CP_COMMIT();
            CP_WAIT(1);
        } else {
            CP_WAIT(0);
        }
        __syncthreads();

        const uint32_t kb = sb + (cur ? SMK1 : SMK0);
        const uint32_t vb = sb + (cur ? SMV1 : SMV0);

        // S = Q K^T  (f16 accum, 16 n-blocks of 8 keys)
        uint32_t S[16][2];
        #pragma unroll
        for (int jp = 0; jp < 8; jp++) {
            uint32_t b0, b1, b2, b3;
            uint32_t base = kb + jp * 1280 + rowoff_k;
            LDSM4(b0, b1, b2, b3, base);
            const uint32_t z = 0;
            MMA_F16(S[2*jp][0],   S[2*jp][1],   QA[0][0], QA[0][1], QA[0][2], QA[0][3], b0, b1, z, z);
            MMA_F16(S[2*jp+1][0], S[2*jp+1][1], QA[0][0], QA[0][1], QA[0][2], QA[0][3], b2, b3, z, z);
            LDSM4(b0, b1, b2, b3, base + 32);
            MMA_F16(S[2*jp][0],   S[2*jp][1],   QA[1][0], QA[1][1], QA[1][2], QA[1][3], b0, b1, S[2*jp][0],   S[2*jp][1]);
            MMA_F16(S[2*jp+1][0], S[2*jp+1][1], QA[1][0], QA[1][1], QA[1][2], QA[1][3], b2, b3, S[2*jp+1][0], S[2*jp+1][1]);
        }
        // P = 2^S (log2e/sqrt(32) folded into Q)
        #pragma unroll
        for (int j = 0; j < 16; j++) { H2EXP(S[j][0]); H2EXP(S[j][1]); }

        // O += P V^T ; rowsum += P * ones
        #pragma unroll
        for (int kk = 0; kk < 8; kk++) {
            uint32_t a0 = S[2*kk][0], a1 = S[2*kk][1], a2 = S[2*kk+1][0], a3 = S[2*kk+1][1];
            MMA_F32(Osum, a0, a1, a2, a3, bone, bone);
            #pragma unroll
            for (int nbp = 0; nbp < 2; nbp++) {
                uint32_t v0, v1, v2, v3;
                LDSM4(v0, v1, v2, v3, vb + nbp * 4352 + rowoff_v + kk * 32);
                MMA_F32(O[2*nbp],     a0, a1, a2, a3, v0, v1);
                MMA_F32(O[2*nbp+1],   a0, a1, a2, a3, v2, v3);
            }
        }
        __syncthreads();
    }

    // normalize + stage O via smem (reuse K region), then coalesced store
    float rs0 = __shfl_sync(0xffffffffu, Osum[0], lane & ~3);
    float rs8 = __shfl_sync(0xffffffffu, Osum[2], lane & ~3);
    float inv0 = 1.f / rs0, inv8 = 1.f / rs8;
    float* Osm = reinterpret_cast<float*>(smem + SMK0);   // [32 d][132]
    int row = lane >> 2;
    int qc = 16 * w + row;
    #pragma unroll
    for (int nb = 0; nb < 4; nb++) {
        int n0 = 8 * nb + 2 * (lane & 3);
        Osm[n0 * 132 + qc]           = O[nb][0] * inv0;
        Osm[(n0 + 1) * 132 + qc]     = O[nb][1] * inv0;
        Osm[n0 * 132 + qc + 8]       = O[nb][2] * inv8;
        Osm[(n0 + 1) * 132 + qc + 8] = O[nb][3] * inv8;
    }
    __syncthreads();
    float* outp = aout + (size_t)(b * C_DIM + h * 32) * N_DIM + q0;
    for (int c = tid; c < 1024; c += 256) {
        int d = c >> 5, qq = (c & 31) * 4;
        float4 v = *reinterpret_cast<const float4*>(&Osm[d * 132 + qq]);
        *reinterpret_cast<float4*>(outp + (size_t)d * N_DIM + qq) = v;
    }
}

// ---------------- launch ----------------
extern "C" void kernel_launch(void* const* d_in, const int* in_sizes, int n_in,
                              void* d_out, int out_size)
{
    const float* x    = (const float*)d_in[0];
    const float* gn_w = (const float*)d_in[1];
    const float* gn_b = (const float*)d_in[2];
    const float* wq   = (const float*)d_in[3];
    const float* bq   = (const float*)d_in[4];
    const float* wk   = (const float*)d_in[5];
    const float* bk   = (const float*)d_in[6];
    const float* wv   = (const float*)d_in[7];
    const float* bv   = (const float*)d_in[8];
    const float* wo   = (const float*)d_in[9];
    const float* bo   = (const float*)d_in[10];
    float* out = (float*)d_out;

    float *scl, *shf, *attn;
    __half *qnd, *knd, *vdn;
    cudaGetSymbolAddress((void**)&scl,  g_scale);
    cudaGetSymbolAddress((void**)&shf,  g_shift);
    cudaGetSymbolAddress((void**)&qnd,  g_qnd);
    cudaGetSymbolAddress((void**)&knd,  g_knd);
    cudaGetSymbolAddress((void**)&vdn,  g_vdn);
    cudaGetSymbolAddress((void**)&attn, g_attn);

    gn_stats_kernel<<<16, 256>>>(x, gn_w, gn_b, scl, shf);

    const float qs = 0.2550466864771404f;   // log2(e)/sqrt(32)
    dim3 ggrid(64, 4, 2);
    gemm256_kernel<<<ggrid, 256>>>(wq, bq, x, scl, shf, nullptr, nullptr, qnd, 1, qs);
    gemm256_kernel<<<ggrid, 256>>>(wk, bk, x, scl, shf, nullptr, nullptr, knd, 1, 1.0f);
    gemm256_kernel<<<ggrid, 256>>>(wv, bv, x, scl, shf, nullptr, nullptr, vdn, 2, 1.0f);

    dim3 fgrid(32, HEADS, B_DIM);
    flash_mma_kernel<<<fgrid, 256>>>(qnd, knd, vdn, attn);

    gemm256_kernel<<<ggrid, 256>>>(wo, bo, attn, nullptr, nullptr, x, out, nullptr, 0, 1.0f);
}

// round 12
// speedup vs baseline: 9.9105x; 1.8486x over previous
#include <cuda_runtime.h>
#include <cuda_fp16.h>
#include <cstdint>
#include <math.h>

#define C_DIM 256
#define N_DIM 4096
#define B_DIM 2
#define HEADS 8
#define BCN (B_DIM * C_DIM * N_DIM)   // 2097152

// ---------------- scratch ----------------
__device__ float g_scale[B_DIM * C_DIM];
__device__ float g_shift[B_DIM * C_DIM];
__device__ __align__(16) __half g_wh[4 * 65536];   // wq,wk,wv,wo fp16
__device__ __align__(16) __half g_xh[BCN];         // normalized x fp16 [b][c][n]
__device__ __align__(16) __half g_qnd[BCN];        // [b*8+h][n][32]
__device__ __align__(16) __half g_knd[BCN];        // [b*8+h][n][32]
__device__ __align__(16) __half g_vdn[BCN];        // [b][c][n]
__device__ __align__(16) __half g_attnh[BCN];      // attention out fp16 [b][c][n]

// ---------------- helpers ----------------
__device__ __forceinline__ uint32_t smem_u32(const void* p) {
    uint32_t a;
    asm("{ .reg .u64 t; cvta.to.shared.u64 t, %1; cvt.u32.u64 %0, t; }" : "=r"(a) : "l"(p));
    return a;
}
__device__ __forceinline__ uint32_t packh(float lo, float hi) {
    uint32_t r; asm("cvt.rn.f16x2.f32 %0, %1, %2;" : "=r"(r) : "f"(hi), "f"(lo)); return r;
}
#define H2EXP(x) asm("ex2.approx.f16x2 %0, %0;" : "+r"(x))

#define CP16(dst, src) asm volatile("cp.async.cg.shared.global [%0], [%1], 16;" :: "r"(dst), "l"(src))
#define CP_COMMIT()    asm volatile("cp.async.commit_group;" ::: "memory")
#define CP_WAIT(n)     asm volatile("cp.async.wait_group %0;" :: "n"(n) : "memory")

#define LDSM4(r0, r1, r2, r3, a) \
    asm volatile("ldmatrix.sync.aligned.m8n8.x4.shared.b16 {%0,%1,%2,%3}, [%4];" \
        : "=r"(r0), "=r"(r1), "=r"(r2), "=r"(r3) : "r"(a))
#define LDSM4T(r0, r1, r2, r3, a) \
    asm volatile("ldmatrix.sync.aligned.m8n8.x4.trans.shared.b16 {%0,%1,%2,%3}, [%4];" \
        : "=r"(r0), "=r"(r1), "=r"(r2), "=r"(r3) : "r"(a))

#define MMA_F16(d0, d1, a0, a1, a2, a3, b0, b1, c0, c1) \
    asm volatile("mma.sync.aligned.m16n8k16.row.col.f16.f16.f16.f16 " \
        "{%0,%1},{%2,%3,%4,%5},{%6,%7},{%8,%9};" \
        : "=r"(d0), "=r"(d1) \
        : "r"(a0), "r"(a1), "r"(a2), "r"(a3), "r"(b0), "r"(b1), "r"(c0), "r"(c1))

#define MMA_F32(D, a0, a1, a2, a3, b0, b1) \
    asm volatile("mma.sync.aligned.m16n8k16.row.col.f32.f16.f16.f32 " \
        "{%0,%1,%2,%3},{%4,%5,%6,%7},{%8,%9},{%0,%1,%2,%3};" \
        : "+f"((D)[0]), "+f"((D)[1]), "+f"((D)[2]), "+f"((D)[3]) \
        : "r"(a0), "r"(a1), "r"(a2), "r"(a3), "r"(b0), "r"(b1))

// ---------------- GroupNorm stats ----------------
__global__ __launch_bounds__(256) void gn_stats_kernel(
    const float* __restrict__ x, const float* __restrict__ gw,
    const float* __restrict__ gb, float* __restrict__ scl, float* __restrict__ shf)
{
    int bg = blockIdx.x;
    int b = bg >> 3, g = bg & 7;
    const float* p = x + (size_t)(b * C_DIM + g * 32) * N_DIM;
    float s = 0.f, s2 = 0.f;
    for (int i = threadIdx.x; i < 131072 / 4; i += 256) {
        float4 v = reinterpret_cast<const float4*>(p)[i];
        s  += v.x + v.y + v.z + v.w;
        s2 += v.x * v.x + v.y * v.y + v.z * v.z + v.w * v.w;
    }
    __shared__ float rs[256], rs2[256];
    rs[threadIdx.x] = s; rs2[threadIdx.x] = s2;
    __syncthreads();
    for (int st = 128; st; st >>= 1) {
        if (threadIdx.x < st) {
            rs[threadIdx.x]  += rs[threadIdx.x + st];
            rs2[threadIdx.x] += rs2[threadIdx.x + st];
        }
        __syncthreads();
    }
    __shared__ float mu_s, rstd_s;
    if (threadIdx.x == 0) {
        float m = rs[0] * (1.f / 131072.f);
        float var = rs2[0] * (1.f / 131072.f) - m * m;
        mu_s = m;
        rstd_s = rsqrtf(var + 1e-5f);
    }
    __syncthreads();
    if (threadIdx.x < 32) {
        int c = g * 32 + threadIdx.x;
        float sc = gw[c] * rstd_s;
        scl[b * C_DIM + c] = sc;
        shf[b * C_DIM + c] = gb[c] - mu_s * sc;
    }
}

// ---------------- weight fp32 -> fp16 ----------------
__global__ __launch_bounds__(256) void wconv_kernel(
    const float* __restrict__ wq, const float* __restrict__ wk,
    const float* __restrict__ wv, const float* __restrict__ wo,
    __half* __restrict__ wh)
{
    int i = blockIdx.x * 256 + threadIdx.x;      // over 65536 float4
    const float* srcs[4] = {wq, wk, wv, wo};
    int which = i >> 14, off = i & 16383;
    float4 v = reinterpret_cast<const float4*>(srcs[which])[off];
    uint2 pk;
    pk.x = packh(v.x, v.y); pk.y = packh(v.z, v.w);
    reinterpret_cast<uint2*>(wh + (size_t)which * 65536)[off] = pk;
}

// ---------------- normalized x -> fp16 ----------------
__global__ __launch_bounds__(256) void xconv_kernel(
    const float* __restrict__ x, const float* __restrict__ scl,
    const float* __restrict__ shf, __half* __restrict__ xh)
{
    int i = blockIdx.x * 256 + threadIdx.x;      // over 524288 float4
    float4 v = reinterpret_cast<const float4*>(x)[i];
    int c = (i >> 10) & 255, b = i >> 18;
    float s = scl[b * 256 + c], t = shf[b * 256 + c];
    uint2 pk;
    pk.x = packh(fmaf(v.x, s, t), fmaf(v.y, s, t));
    pk.y = packh(fmaf(v.z, s, t), fmaf(v.w, s, t));
    reinterpret_cast<uint2*>(xh)[i] = pk;
}

// ---------------- HMMA GEMM: Y[o,n] = W[o,:] @ X[:,n], K=256 ----------------
// grid (32 n-tiles, 2 o-tiles, 2 b), 256 threads. CTA tile 128o x 128n, BK=32 x 8 chunks.
// mode 0: fp32 acc+bias+resid -> Yf [b][o][n]
// mode 1: fp16 (acc+bias)*outscale -> Yh [(b*8+o/32)][n][o%32]
// mode 2: fp16 acc+bias -> Yh [b][o][n]
// smem: W [2][128][40h] @0 (20480B), X [2][32][136h] @20480 (17408B); mode1 staging reuses [w*4224].
__global__ __launch_bounds__(256) void hgemm_kernel(
    const __half* __restrict__ Wh, const float* __restrict__ bias,
    const __half* __restrict__ Xh, const float* __restrict__ resid,
    float* __restrict__ Yf, __half* __restrict__ Yh, int mode, float outscale)
{
    __shared__ __align__(16) char sm[37888];
    const int n0 = blockIdx.x * 128;
    const int otile = blockIdx.y;
    const int b = blockIdx.z;
    const int tid = threadIdx.x, w = tid >> 5, lane = tid & 31;
    const int warp_o = (w >> 1) * 32, warp_n = (w & 1) * 64;
    const uint32_t sb = smem_u32(sm);

    const __half* Wp = Wh + (size_t)otile * 128 * 256;
    const __half* Xp = Xh + (size_t)b * C_DIM * N_DIM;

    auto prefW = [&](int k0, int buf) {
        #pragma unroll
        for (int r = 0; r < 2; r++) {
            int idx = tid + r * 256;
            int o = idx >> 2, seg = idx & 3;
            CP16(sb + buf * 10240 + o * 80 + seg * 16,
                 Wp + (size_t)o * 256 + k0 + seg * 8);
        }
    };
    auto prefX = [&](int k0, int buf) {
        #pragma unroll
        for (int r = 0; r < 2; r++) {
            int idx = tid + r * 256;
            int k = idx >> 4, seg = idx & 15;
            CP16(sb + 20480 + buf * 8704 + k * 272 + seg * 16,
                 Xp + (size_t)(k0 + k) * N_DIM + n0 + seg * 8);
        }
    };

    prefW(0, 0); prefX(0, 0); CP_COMMIT();

    float acc[2][8][4] = {};
    for (int kc = 0; kc < 8; kc++) {
        int buf = kc & 1;
        if (kc < 7) { prefW((kc + 1) * 32, buf ^ 1); prefX((kc + 1) * 32, buf ^ 1); CP_COMMIT(); CP_WAIT(1); }
        else CP_WAIT(0);
        __syncthreads();
        uint32_t wb = sb + buf * 10240;
        uint32_t xb = sb + 20480 + buf * 8704;
        #pragma unroll
        for (int kk = 0; kk < 2; kk++) {
            uint32_t a[2][4];
            #pragma unroll
            for (int m = 0; m < 2; m++) {
                uint32_t addr = wb + (warp_o + m * 16 + (lane & 15)) * 80 + kk * 32 + ((lane & 16) ? 16 : 0);
                LDSM4(a[m][0], a[m][1], a[m][2], a[m][3], addr);
            }
            #pragma unroll
            for (int j = 0; j < 4; j++) {
                uint32_t b0, b1, b2, b3;
                uint32_t addr = xb + (kk * 16 + (lane & 15)) * 272 + (warp_n + j * 16 + ((lane >> 4) * 8)) * 2;
                LDSM4T(b0, b1, b2, b3, addr);
                MMA_F32(acc[0][2*j],   a[0][0], a[0][1], a[0][2], a[0][3], b0, b1);
                MMA_F32(acc[0][2*j+1], a[0][0], a[0][1], a[0][2], a[0][3], b2, b3);
                MMA_F32(acc[1][2*j],   a[1][0], a[1][1], a[1][2], a[1][3], b0, b1);
                MMA_F32(acc[1][2*j+1], a[1][0], a[1][1], a[1][2], a[1][3], b2, b3);
            }
        }
        __syncthreads();
    }

    const int rr = lane >> 2, cc = (lane & 3) * 2;
    if (mode == 0) {
        const size_t ybase = (size_t)b * C_DIM * N_DIM;
        #pragma unroll
        for (int m = 0; m < 2; m++) {
            #pragma unroll
            for (int j = 0; j < 8; j++) {
                int o = otile * 128 + warp_o + m * 16 + rr;
                int n = n0 + warp_n + j * 8 + cc;
                float bo = bias[o], bo8 = bias[o + 8];
                size_t off = ybase + (size_t)o * N_DIM + n;
                float2 r0 = *reinterpret_cast<const float2*>(resid + off);
                float2 r1 = *reinterpret_cast<const float2*>(resid + off + 8 * N_DIM);
                float2 v0 = {acc[m][j][0] + bo + r0.x, acc[m][j][1] + bo + r0.y};
                float2 v1 = {acc[m][j][2] + bo8 + r1.x, acc[m][j][3] + bo8 + r1.y};
                *reinterpret_cast<float2*>(Yf + off) = v0;
                *reinterpret_cast<float2*>(Yf + off + 8 * N_DIM) = v1;
            }
        }
    } else if (mode == 2) {
        const size_t ybase = (size_t)b * C_DIM * N_DIM;
        #pragma unroll
        for (int m = 0; m < 2; m++) {
            #pragma unroll
            for (int j = 0; j < 8; j++) {
                int o = otile * 128 + warp_o + m * 16 + rr;
                int n = n0 + warp_n + j * 8 + cc;
                float bo = bias[o], bo8 = bias[o + 8];
                *reinterpret_cast<uint32_t*>(Yh + ybase + (size_t)o * N_DIM + n) =
                    packh(acc[m][j][0] + bo, acc[m][j][1] + bo);
                *reinterpret_cast<uint32_t*>(Yh + ybase + (size_t)(o + 8) * N_DIM + n) =
                    packh(acc[m][j][2] + bo8, acc[m][j][3] + bo8);
            }
        }
    } else {
        // stage warp tile [32 o][66 h] fp16, then emit [n][32] coalesced
        char* stg = sm + w * 4224;
        const int obase = otile * 128 + warp_o;
        #pragma unroll
        for (int m = 0; m < 2; m++) {
            #pragma unroll
            for (int j = 0; j < 8; j++) {
                int row = m * 16 + rr;
                int col = j * 8 + cc;
                float bo = bias[obase + row], bo8 = bias[obase + row + 8];
                *reinterpret_cast<uint32_t*>(stg + row * 132 + col * 2) =
                    packh((acc[m][j][0] + bo) * outscale, (acc[m][j][1] + bo) * outscale);
                *reinterpret_cast<uint32_t*>(stg + (row + 8) * 132 + col * 2) =
                    packh((acc[m][j][2] + bo8) * outscale, (acc[m][j][3] + bo8) * outscale);
            }
        }
        __syncwarp();
        int hh = obase >> 5;
        __half* qp = Yh + ((size_t)(b * HEADS + hh) * N_DIM + n0 + warp_n) * 32;
        const ushort* sh = reinterpret_cast<const ushort*>(stg);
        int dl2 = lane & 15;
        #pragma unroll
        for (int i = 0; i < 32; i++) {
            int nloc = i * 2 + (lane >> 4);
            uint32_t h0 = sh[(2 * dl2) * 66 + nloc];
            uint32_t h1 = sh[(2 * dl2 + 1) * 66 + nloc];
            *reinterpret_cast<uint32_t*>(reinterpret_cast<char*>(qp) + (size_t)nloc * 64 + dl2 * 4) =
                h0 | (h1 << 16);
        }
    }
}

// ---------------- flash attention via mma.sync fp16 (proven R7, fp16 output) ----------------
#define SMQ  0
#define SMK0 10240
#define SMK1 20480
#define SMV0 30720
#define SMV1 39424

__global__ __launch_bounds__(256) void flash_mma_kernel(
    const __half* __restrict__ Qg_, const __half* __restrict__ Kg_,
    const __half* __restrict__ Vg_, __half* __restrict__ aout)
{
    __shared__ __align__(16) char smem[48128];
    const int q0 = blockIdx.x * 128;
    const int h = blockIdx.y, b = blockIdx.z;
    const int tid = threadIdx.x;
    const int w = tid >> 5, lane = tid & 31;
    const uint32_t sb = smem_u32(smem);

    const int bh = b * HEADS + h;
    const __half* Qg = Qg_ + (size_t)bh * N_DIM * 32;
    const __half* Kg = Kg_ + (size_t)bh * N_DIM * 32;
    const __half* Vg = Vg_ + (size_t)(b * C_DIM + h * 32) * N_DIM;

    for (int c = tid; c < 512; c += 256) {
        int row = c >> 2, seg = c & 3;
        uint4 v = *reinterpret_cast<const uint4*>(Qg + (size_t)(q0 + row) * 32 + seg * 8);
        *reinterpret_cast<uint4*>(smem + SMQ + row * 80 + seg * 16) = v;
    }

    auto prefK = [&](int m0, uint32_t base) {
        for (int c = tid; c < 512; c += 256) {
            int row = c >> 2, seg = c & 3;
            CP16(sb + base + row * 80 + seg * 16,
                 Kg + (size_t)(m0 + row) * 32 + seg * 8);
        }
    };
    auto prefV = [&](int m0, uint32_t base) {
        for (int c = tid; c < 512; c += 256) {
            int d = c >> 4, seg = c & 15;
            CP16(sb + base + d * 272 + seg * 16,
                 Vg + (size_t)d * N_DIM + m0 + seg * 8);
        }
    };
    prefK(0, SMK0);
    prefV(0, SMV0);
    CP_COMMIT();
    __syncthreads();

    uint32_t QA[2][4];
    {
        uint32_t qaddr = sb + SMQ + (16 * w + (lane & 15)) * 80 + ((lane & 16) ? 16 : 0);
        LDSM4(QA[0][0], QA[0][1], QA[0][2], QA[0][3], qaddr);
        LDSM4(QA[1][0], QA[1][1], QA[1][2], QA[1][3], qaddr + 32);
    }

    const uint32_t rowoff_k = ((lane & 7) + ((lane & 16) ? 8 : 0)) * 80 + ((lane & 8) ? 16 : 0);
    const uint32_t rowoff_v = ((lane & 7) + ((lane & 16) ? 8 : 0)) * 272 + ((lane & 8) ? 16 : 0);
    const uint32_t bone = ((lane >> 2) == 0) ? 0x3C003C00u : 0u;

    float O[4][4] = {};
    float Osum[4] = {};

    for (int it = 0; it < 32; it++) {
        const int cur = it & 1;
        if (it + 1 < 32) {
            prefK(128 * (it + 1), cur ? SMK0 : SMK1);
            prefV(128 * (it + 1), cur ? SMV0 : SMV1);
            CP_COMMIT();
            CP_WAIT(1);
        } else {
            CP_WAIT(0);
        }
        __syncthreads();

        const uint32_t kb = sb + (cur ? SMK1 : SMK0);
        const uint32_t vb = sb + (cur ? SMV1 : SMV0);

        uint32_t S[16][2];
        #pragma unroll
        for (int jp = 0; jp < 8; jp++) {
            uint32_t b0, b1, b2, b3;
            uint32_t base = kb + jp * 1280 + rowoff_k;
            LDSM4(b0, b1, b2, b3, base);
            const uint32_t z = 0;
            MMA_F16(S[2*jp][0],   S[2*jp][1],   QA[0][0], QA[0][1], QA[0][2], QA[0][3], b0, b1, z, z);
            MMA_F16(S[2*jp+1][0], S[2*jp+1][1], QA[0][0], QA[0][1], QA[0][2], QA[0][3], b2, b3, z, z);
            LDSM4(b0, b1, b2, b3, base + 32);
            MMA_F16(S[2*jp][0],   S[2*jp][1],   QA[1][0], QA[1][1], QA[1][2], QA[1][3], b0, b1, S[2*jp][0],   S[2*jp][1]);
            MMA_F16(S[2*jp+1][0], S[2*jp+1][1], QA[1][0], QA[1][1], QA[1][2], QA[1][3], b2, b3, S[2*jp+1][0], S[2*jp+1][1]);
        }
        #pragma unroll
        for (int j = 0; j < 16; j++) { H2EXP(S[j][0]); H2EXP(S[j][1]); }

        #pragma unroll
        for (int kk = 0; kk < 8; kk++) {
            uint32_t a0 = S[2*kk][0], a1 = S[2*kk][1], a2 = S[2*kk+1][0], a3 = S[2*kk+1][1];
            MMA_F32(Osum, a0, a1, a2, a3, bone, bone);
            #pragma unroll
            for (int nbp = 0; nbp < 2; nbp++) {
                uint32_t v0, v1, v2, v3;
                LDSM4(v0, v1, v2, v3, vb + nbp * 4352 + rowoff_v + kk * 32);
                MMA_F32(O[2*nbp],   a0, a1, a2, a3, v0, v1);
                MMA_F32(O[2*nbp+1], a0, a1, a2, a3, v2, v3);
            }
        }
        __syncthreads();
    }

    float rs0 = __shfl_sync(0xffffffffu, Osum[0], lane & ~3);
    float rs8 = __shfl_sync(0xffffffffu, Osum[2], lane & ~3);
    float inv0 = 1.f / rs0, inv8 = 1.f / rs8;
    float* Osm = reinterpret_cast<float*>(smem + SMK0);
    int row = lane >> 2;
    int qc = 16 * w + row;
    #pragma unroll
    for (int nb = 0; nb < 4; nb++) {
        int n0 = 8 * nb + 2 * (lane & 3);
        Osm[n0 * 132 + qc]           = O[nb][0] * inv0;
        Osm[(n0 + 1) * 132 + qc]     = O[nb][1] * inv0;
        Osm[n0 * 132 + qc + 8]       = O[nb][2] * inv8;
        Osm[(n0 + 1) * 132 + qc + 8] = O[nb][3] * inv8;
    }
    __syncthreads();
    __half* outp = aout + (size_t)(b * C_DIM + h * 32) * N_DIM + q0;
    for (int c = tid; c < 1024; c += 256) {
        int d = c >> 5, qq = (c & 31) * 4;
        float4 v = *reinterpret_cast<const float4*>(&Osm[d * 132 + qq]);
        uint2 pk;
        pk.x = packh(v.x, v.y); pk.y = packh(v.z, v.w);
        *reinterpret_cast<uint2*>(outp + (size_t)d * N_DIM + qq) = pk;
    }
}

// ---------------- launch ----------------
extern "C" void kernel_launch(void* const* d_in, const int* in_sizes, int n_in,
                              void* d_out, int out_size)
{
    const float* x    = (const float*)d_in[0];
    const float* gn_w = (const float*)d_in[1];
    const float* gn_b = (const float*)d_in[2];
    const float* wq   = (const float*)d_in[3];
    const float* bq   = (const float*)d_in[4];
    const float* wk   = (const float*)d_in[5];
    const float* bk   = (const float*)d_in[6];
    const float* wv   = (const float*)d_in[7];
    const float* bv   = (const float*)d_in[8];
    const float* wo   = (const float*)d_in[9];
    const float* bo   = (const float*)d_in[10];
    float* out = (float*)d_out;

    float *scl, *shf;
    __half *wh, *xh, *qnd, *knd, *vdn, *attnh;
    cudaGetSymbolAddress((void**)&scl,   g_scale);
    cudaGetSymbolAddress((void**)&shf,   g_shift);
    cudaGetSymbolAddress((void**)&wh,    g_wh);
    cudaGetSymbolAddress((void**)&xh,    g_xh);
    cudaGetSymbolAddress((void**)&qnd,   g_qnd);
    cudaGetSymbolAddress((void**)&knd,   g_knd);
    cudaGetSymbolAddress((void**)&vdn,   g_vdn);
    cudaGetSymbolAddress((void**)&attnh, g_attnh);

    gn_stats_kernel<<<16, 256>>>(x, gn_w, gn_b, scl, shf);
    wconv_kernel<<<256, 256>>>(wq, wk, wv, wo, wh);
    xconv_kernel<<<2048, 256>>>(x, scl, shf, xh);

    const float qs = 0.2550466864771404f;   // log2(e)/sqrt(32)
    dim3 ggrid(32, 2, 2);
    hgemm_kernel<<<ggrid, 256>>>(wh,           bq, xh,    nullptr, nullptr, qnd, 1, qs);
    hgemm_kernel<<<ggrid, 256>>>(wh + 65536,   bk, xh,    nullptr, nullptr, knd, 1, 1.0f);
    hgemm_kernel<<<ggrid, 256>>>(wh + 131072,  bv, xh,    nullptr, nullptr, vdn, 2, 1.0f);

    dim3 fgrid(32, HEADS, B_DIM);
    flash_mma_kernel<<<fgrid, 256>>>(qnd, knd, vdn, attnh);

    hgemm_kernel<<<ggrid, 256>>>(wh + 196608,  bo, attnh, x, out, nullptr, 0, 1.0f);
}

// round 13
// speedup vs baseline: 11.3924x; 1.1495x over previous
#include <cuda_runtime.h>
#include <cuda_fp16.h>
#include <cstdint>
#include <math.h>

#define C_DIM 256
#define N_DIM 4096
#define B_DIM 2
#define HEADS 8
#define BCN (B_DIM * C_DIM * N_DIM)   // 2097152

// ---------------- scratch ----------------
__device__ float g_scale[B_DIM * C_DIM];
__device__ float g_shift[B_DIM * C_DIM];
__device__ float g_psum[128], g_psum2[128];
__device__ __align__(16) __half g_wh[4 * 65536];   // wq,wk,wv,wo fp16
__device__ __align__(16) __half g_xh[BCN];         // normalized x fp16 [b][c][n]
__device__ __align__(16) __half g_qnd[BCN];        // [b*8+h][n][32]
__device__ __align__(16) __half g_knd[BCN];        // [b*8+h][n][32]
__device__ __align__(16) __half g_vdn[BCN];        // [b][c][n]
__device__ __align__(16) __half g_attnh[BCN];      // attention out fp16 [b][c][n]

// ---------------- helpers ----------------
__device__ __forceinline__ uint32_t smem_u32(const void* p) {
    uint32_t a;
    asm("{ .reg .u64 t; cvta.to.shared.u64 t, %1; cvt.u32.u64 %0, t; }" : "=r"(a) : "l"(p));
    return a;
}
__device__ __forceinline__ uint32_t packh(float lo, float hi) {
    uint32_t r; asm("cvt.rn.f16x2.f32 %0, %1, %2;" : "=r"(r) : "f"(hi), "f"(lo)); return r;
}
#define H2EXP(x) asm("ex2.approx.f16x2 %0, %0;" : "+r"(x))

#define CP16(dst, src) asm volatile("cp.async.cg.shared.global [%0], [%1], 16;" :: "r"(dst), "l"(src))
#define CP_COMMIT()    asm volatile("cp.async.commit_group;" ::: "memory")
#define CP_WAIT(n)     asm volatile("cp.async.wait_group %0;" :: "n"(n) : "memory")

#define LDSM4(r0, r1, r2, r3, a) \
    asm volatile("ldmatrix.sync.aligned.m8n8.x4.shared.b16 {%0,%1,%2,%3}, [%4];" \
        : "=r"(r0), "=r"(r1), "=r"(r2), "=r"(r3) : "r"(a))
#define LDSM4T(r0, r1, r2, r3, a) \
    asm volatile("ldmatrix.sync.aligned.m8n8.x4.trans.shared.b16 {%0,%1,%2,%3}, [%4];" \
        : "=r"(r0), "=r"(r1), "=r"(r2), "=r"(r3) : "r"(a))

#define MMA_F16(d0, d1, a0, a1, a2, a3, b0, b1, c0, c1) \
    asm volatile("mma.sync.aligned.m16n8k16.row.col.f16.f16.f16.f16 " \
        "{%0,%1},{%2,%3,%4,%5},{%6,%7},{%8,%9};" \
        : "=r"(d0), "=r"(d1) \
        : "r"(a0), "r"(a1), "r"(a2), "r"(a3), "r"(b0), "r"(b1), "r"(c0), "r"(c1))

#define MMA_F32(D, a0, a1, a2, a3, b0, b1) \
    asm volatile("mma.sync.aligned.m16n8k16.row.col.f32.f16.f16.f32 " \
        "{%0,%1,%2,%3},{%4,%5,%6,%7},{%8,%9},{%0,%1,%2,%3};" \
        : "+f"((D)[0]), "+f"((D)[1]), "+f"((D)[2]), "+f"((D)[3]) \
        : "r"(a0), "r"(a1), "r"(a2), "r"(a3), "r"(b0), "r"(b1))

// ---------------- GN phase A: 128 partial-reduce CTAs + 64 wconv CTAs ----------------
__global__ __launch_bounds__(256) void gnA_kernel(
    const float* __restrict__ x,
    const float* __restrict__ wq, const float* __restrict__ wk,
    const float* __restrict__ wv, const float* __restrict__ wo,
    float* __restrict__ psum, float* __restrict__ psum2, __half* __restrict__ wh)
{
    if (blockIdx.x < 128) {
        int cta = blockIdx.x;
        const float* p = x + (size_t)cta * 16384;
        float s = 0.f, s2 = 0.f;
        #pragma unroll 4
        for (int i = threadIdx.x; i < 4096; i += 256) {
            float4 v = reinterpret_cast<const float4*>(p)[i];
            s  += v.x + v.y + v.z + v.w;
            s2 += v.x * v.x + v.y * v.y + v.z * v.z + v.w * v.w;
        }
        __shared__ float rs[256], rs2[256];
        rs[threadIdx.x] = s; rs2[threadIdx.x] = s2;
        __syncthreads();
        for (int st = 128; st; st >>= 1) {
            if (threadIdx.x < st) {
                rs[threadIdx.x]  += rs[threadIdx.x + st];
                rs2[threadIdx.x] += rs2[threadIdx.x + st];
            }
            __syncthreads();
        }
        if (threadIdx.x == 0) { psum[cta] = rs[0]; psum2[cta] = rs2[0]; }
    } else {
        const float* srcs[4] = {wq, wk, wv, wo};
        int base = (blockIdx.x - 128) * 1024 + threadIdx.x;  // over 65536 float4
        #pragma unroll
        for (int r = 0; r < 4; r++) {
            int i = base + r * 256;
            int which = i >> 14, off = i & 16383;
            float4 v = reinterpret_cast<const float4*>(srcs[which])[off];
            uint2 pk;
            pk.x = packh(v.x, v.y); pk.y = packh(v.z, v.w);
            reinterpret_cast<uint2*>(g_wh + (size_t)which * 65536)[off] = pk;
        }
    }
}

// ---------------- GN phase B: finalize scale/shift (1 CTA, 512 thr) ----------------
__global__ __launch_bounds__(512) void gnB_kernel(
    const float* __restrict__ psum, const float* __restrict__ psum2,
    const float* __restrict__ gw, const float* __restrict__ gb,
    float* __restrict__ scl, float* __restrict__ shf)
{
    int t = threadIdx.x;
    int g16 = t >> 5, c = t & 31;
    float s = 0.f, s2 = 0.f;
    #pragma unroll
    for (int i = 0; i < 8; i++) { s += psum[g16 * 8 + i]; s2 += psum2[g16 * 8 + i]; }
    float m = s * (1.f / 131072.f);
    float var = s2 * (1.f / 131072.f) - m * m;
    float rstd = rsqrtf(var + 1e-5f);
    int b = g16 >> 3, g = g16 & 7;
    int ch = g * 32 + c;
    float sc = gw[ch] * rstd;
    scl[b * C_DIM + ch] = sc;
    shf[b * C_DIM + ch] = gb[ch] - m * sc;
}

// ---------------- normalized x -> fp16 ----------------
__global__ __launch_bounds__(256) void xconv_kernel(
    const float* __restrict__ x, const float* __restrict__ scl,
    const float* __restrict__ shf, __half* __restrict__ xh)
{
    int i = blockIdx.x * 256 + threadIdx.x;      // over 524288 float4
    float4 v = reinterpret_cast<const float4*>(x)[i];
    int c = (i >> 10) & 255, b = i >> 18;
    float s = scl[b * 256 + c], t = shf[b * 256 + c];
    uint2 pk;
    pk.x = packh(fmaf(v.x, s, t), fmaf(v.y, s, t));
    pk.y = packh(fmaf(v.z, s, t), fmaf(v.w, s, t));
    reinterpret_cast<uint2*>(xh)[i] = pk;
}

// ================= HMMA GEMM core (128o x 128n, K=256) =================
struct GemmAcc { float a[2][8][4]; };

__device__ __forceinline__ void hgemm_core(
    const __half* __restrict__ Wp, const __half* __restrict__ Xp,
    uint32_t sb, int n0, int tid, int w, int lane, int warp_o, int warp_n,
    GemmAcc& A)
{
    auto prefW = [&](int k0, int buf) {
        #pragma unroll
        for (int r = 0; r < 2; r++) {
            int idx = tid + r * 256;
            int o = idx >> 2, seg = idx & 3;
            CP16(sb + buf * 10240 + o * 80 + seg * 16,
                 Wp + (size_t)o * 256 + k0 + seg * 8);
        }
    };
    auto prefX = [&](int k0, int buf) {
        #pragma unroll
        for (int r = 0; r < 2; r++) {
            int idx = tid + r * 256;
            int k = idx >> 4, seg = idx & 15;
            CP16(sb + 20480 + buf * 8704 + k * 272 + seg * 16,
                 Xp + (size_t)(k0 + k) * N_DIM + n0 + seg * 8);
        }
    };
    prefW(0, 0); prefX(0, 0); CP_COMMIT();
    for (int kc = 0; kc < 8; kc++) {
        int buf = kc & 1;
        if (kc < 7) { prefW((kc + 1) * 32, buf ^ 1); prefX((kc + 1) * 32, buf ^ 1); CP_COMMIT(); CP_WAIT(1); }
        else CP_WAIT(0);
        __syncthreads();
        uint32_t wb = sb + buf * 10240;
        uint32_t xb = sb + 20480 + buf * 8704;
        #pragma unroll
        for (int kk = 0; kk < 2; kk++) {
            uint32_t a[2][4];
            #pragma unroll
            for (int m = 0; m < 2; m++) {
                uint32_t addr = wb + (warp_o + m * 16 + (lane & 15)) * 80 + kk * 32 + ((lane & 16) ? 16 : 0);
                LDSM4(a[m][0], a[m][1], a[m][2], a[m][3], addr);
            }
            #pragma unroll
            for (int j = 0; j < 4; j++) {
                uint32_t b0, b1, b2, b3;
                uint32_t addr = xb + (kk * 16 + (lane & 15)) * 272 + (warp_n + j * 16 + ((lane >> 4) * 8)) * 2;
                LDSM4T(b0, b1, b2, b3, addr);
                MMA_F32(A.a[0][2*j],   a[0][0], a[0][1], a[0][2], a[0][3], b0, b1);
                MMA_F32(A.a[0][2*j+1], a[0][0], a[0][1], a[0][2], a[0][3], b2, b3);
                MMA_F32(A.a[1][2*j],   a[1][0], a[1][1], a[1][2], a[1][3], b0, b1);
                MMA_F32(A.a[1][2*j+1], a[1][0], a[1][1], a[1][2], a[1][3], b2, b3);
            }
        }
        __syncthreads();
    }
}

// ---------------- fused QKV GEMM: grid (32, 6, 2) ----------------
__global__ __launch_bounds__(256) void qkv_gemm_kernel(
    const __half* __restrict__ Wh,
    const float* __restrict__ bq, const float* __restrict__ bk, const float* __restrict__ bv,
    const __half* __restrict__ Xh,
    __half* __restrict__ qnd, __half* __restrict__ knd, __half* __restrict__ vdn,
    float qs)
{
    __shared__ __align__(16) char sm[37888];
    const int n0 = blockIdx.x * 128;
    const int my = blockIdx.y;
    const int mat = my >> 1, otile = my & 1;
    const int b = blockIdx.z;
    const int tid = threadIdx.x, w = tid >> 5, lane = tid & 31;
    const int warp_o = (w >> 1) * 32, warp_n = (w & 1) * 64;
    const uint32_t sb = smem_u32(sm);

    const float* bias = (mat == 0) ? bq : (mat == 1) ? bk : bv;
    const float outscale = (mat == 0) ? qs : 1.0f;
    __half* Yh = (mat == 0) ? qnd : (mat == 1) ? knd : vdn;

    GemmAcc A = {};
    hgemm_core(Wh + (size_t)mat * 65536 + (size_t)otile * 128 * 256,
               Xh + (size_t)b * C_DIM * N_DIM, sb, n0, tid, w, lane, warp_o, warp_n, A);

    const int rr = lane >> 2, cc = (lane & 3) * 2;
    if (mat == 2) {
        // V: fp16 [b][o][n]
        const size_t ybase = (size_t)b * C_DIM * N_DIM;
        #pragma unroll
        for (int m = 0; m < 2; m++) {
            #pragma unroll
            for (int j = 0; j < 8; j++) {
                int o = otile * 128 + warp_o + m * 16 + rr;
                int n = n0 + warp_n + j * 8 + cc;
                float bo = bias[o], bo8 = bias[o + 8];
                *reinterpret_cast<uint32_t*>(Yh + ybase + (size_t)o * N_DIM + n) =
                    packh(A.a[m][j][0] + bo, A.a[m][j][1] + bo);
                *reinterpret_cast<uint32_t*>(Yh + ybase + (size_t)(o + 8) * N_DIM + n) =
                    packh(A.a[m][j][2] + bo8, A.a[m][j][3] + bo8);
            }
        }
    } else {
        // Q/K: fp16 [(b*8+o/32)][n][o%32] via smem transpose staging
        char* stg = sm + w * 4224;
        const int obase = otile * 128 + warp_o;
        #pragma unroll
        for (int m = 0; m < 2; m++) {
            #pragma unroll
            for (int j = 0; j < 8; j++) {
                int row = m * 16 + rr;
                int col = j * 8 + cc;
                float bo = bias[obase + row], bo8 = bias[obase + row + 8];
                *reinterpret_cast<uint32_t*>(stg + row * 132 + col * 2) =
                    packh((A.a[m][j][0] + bo) * outscale, (A.a[m][j][1] + bo) * outscale);
                *reinterpret_cast<uint32_t*>(stg + (row + 8) * 132 + col * 2) =
                    packh((A.a[m][j][2] + bo8) * outscale, (A.a[m][j][3] + bo8) * outscale);
            }
        }
        __syncwarp();
        int hh = obase >> 5;
        __half* qp = Yh + ((size_t)(b * HEADS + hh) * N_DIM + n0 + warp_n) * 32;
        const ushort* sh = reinterpret_cast<const ushort*>(stg);
        int dl2 = lane & 15;
        #pragma unroll
        for (int i = 0; i < 32; i++) {
            int nloc = i * 2 + (lane >> 4);
            uint32_t h0 = sh[(2 * dl2) * 66 + nloc];
            uint32_t h1 = sh[(2 * dl2 + 1) * 66 + nloc];
            *reinterpret_cast<uint32_t*>(reinterpret_cast<char*>(qp) + (size_t)nloc * 64 + dl2 * 4) =
                h0 | (h1 << 16);
        }
    }
}

// ---------------- out-proj GEMM (mode 0): fp32 + bias + residual ----------------
__global__ __launch_bounds__(256) void oproj_kernel(
    const __half* __restrict__ Wh, const float* __restrict__ bias,
    const __half* __restrict__ Xh, const float* __restrict__ resid,
    float* __restrict__ Yf)
{
    __shared__ __align__(16) char sm[37888];
    const int n0 = blockIdx.x * 128;
    const int otile = blockIdx.y;
    const int b = blockIdx.z;
    const int tid = threadIdx.x, w = tid >> 5, lane = tid & 31;
    const int warp_o = (w >> 1) * 32, warp_n = (w & 1) * 64;
    const uint32_t sb = smem_u32(sm);

    GemmAcc A = {};
    hgemm_core(Wh + (size_t)otile * 128 * 256,
               Xh + (size_t)b * C_DIM * N_DIM, sb, n0, tid, w, lane, warp_o, warp_n, A);

    const int rr = lane >> 2, cc = (lane & 3) * 2;
    const size_t ybase = (size_t)b * C_DIM * N_DIM;
    #pragma unroll
    for (int m = 0; m < 2; m++) {
        #pragma unroll
        for (int j = 0; j < 8; j++) {
            int o = otile * 128 + warp_o + m * 16 + rr;
            int n = n0 + warp_n + j * 8 + cc;
            float bo = bias[o], bo8 = bias[o + 8];
            size_t off = ybase + (size_t)o * N_DIM + n;
            float2 r0 = *reinterpret_cast<const float2*>(resid + off);
            float2 r1 = *reinterpret_cast<const float2*>(resid + off + 8 * N_DIM);
            float2 v0 = {A.a[m][j][0] + bo + r0.x, A.a[m][j][1] + bo + r0.y};
            float2 v1 = {A.a[m][j][2] + bo8 + r1.x, A.a[m][j][3] + bo8 + r1.y};
            *reinterpret_cast<float2*>(Yf + off) = v0;
            *reinterpret_cast<float2*>(Yf + off + 8 * N_DIM) = v1;
        }
    }
}

// ---------------- flash attention: 256-q CTA, 512 threads ----------------
// dynamic smem layout:
//   Q:  [256 rows][80 B] @ 0      (20480)
//   K0: [128 rows][80 B] @ 20480  (10240)
//   K1: [128 rows][80 B] @ 30720  (10240)
//   V0: [32 rows][272 B] @ 40960  (8704)
//   V1: [32 rows][272 B] @ 49664  (8704)  -> total 58368
// O staging reuses @20480: [32 d][260 f32] = 33280 B.
#define FSMQ  0
#define FSMK0 20480
#define FSMK1 30720
#define FSMV0 40960
#define FSMV1 49664
#define FSM_TOTAL 58368

__global__ __launch_bounds__(512) void flash_mma_kernel(
    const __half* __restrict__ Qg_, const __half* __restrict__ Kg_,
    const __half* __restrict__ Vg_, __half* __restrict__ aout)
{
    extern __shared__ __align__(16) char smem[];
    const int q0 = blockIdx.x * 256;
    const int h = blockIdx.y, b = blockIdx.z;
    const int tid = threadIdx.x;
    const int w = tid >> 5, lane = tid & 31;
    const uint32_t sb = smem_u32(smem);

    const int bh = b * HEADS + h;
    const __half* Qg = Qg_ + (size_t)bh * N_DIM * 32;
    const __half* Kg = Kg_ + (size_t)bh * N_DIM * 32;
    const __half* Vg = Vg_ + (size_t)(b * C_DIM + h * 32) * N_DIM;

    // Q tile: 256 rows x 32h
    for (int c = tid; c < 1024; c += 512) {
        int row = c >> 2, seg = c & 3;
        uint4 v = *reinterpret_cast<const uint4*>(Qg + (size_t)(q0 + row) * 32 + seg * 8);
        *reinterpret_cast<uint4*>(smem + FSMQ + row * 80 + seg * 16) = v;
    }

    auto prefK = [&](int m0, uint32_t base) {
        int row = tid >> 2, seg = tid & 3;
        CP16(sb + base + row * 80 + seg * 16,
             Kg + (size_t)(m0 + row) * 32 + seg * 8);
    };
    auto prefV = [&](int m0, uint32_t base) {
        int d = tid >> 4, seg = tid & 15;
        CP16(sb + base + d * 272 + seg * 16,
             Vg + (size_t)d * N_DIM + m0 + seg * 8);
    };
    prefK(0, FSMK0);
    prefV(0, FSMV0);
    CP_COMMIT();
    __syncthreads();

    uint32_t QA[2][4];
    {
        uint32_t qaddr = sb + FSMQ + (16 * w + (lane & 15)) * 80 + ((lane & 16) ? 16 : 0);
        LDSM4(QA[0][0], QA[0][1], QA[0][2], QA[0][3], qaddr);
        LDSM4(QA[1][0], QA[1][1], QA[1][2], QA[1][3], qaddr + 32);
    }

    const uint32_t rowoff_k = ((lane & 7) + ((lane & 16) ? 8 : 0)) * 80 + ((lane & 8) ? 16 : 0);
    const uint32_t rowoff_v = ((lane & 7) + ((lane & 16) ? 8 : 0)) * 272 + ((lane & 8) ? 16 : 0);
    const uint32_t bone = ((lane >> 2) == 0) ? 0x3C003C00u : 0u;

    float O[4][4] = {};
    float Osum[4] = {};

    for (int it = 0; it < 32; it++) {
        const int cur = it & 1;
        if (it + 1 < 32) {
            prefK(128 * (it + 1), cur ? FSMK0 : FSMK1);
            prefV(128 * (it + 1), cur ? FSMV0 : FSMV1);
            CP_COMMIT();
            CP_WAIT(1);
        } else {
            CP_WAIT(0);
        }
        __syncthreads();

        const uint32_t kb = sb + (cur ? FSMK1 : FSMK0);
        const uint32_t vb = sb + (cur ? FSMV1 : FSMV0);

        uint32_t S[16][2];
        #pragma unroll
        for (int jp = 0; jp < 8; jp++) {
            uint32_t b0, b1, b2, b3;
            uint32_t base = kb + jp * 1280 + rowoff_k;
            LDSM4(b0, b1, b2, b3, base);
            const uint32_t z = 0;
            MMA_F16(S[2*jp][0],   S[2*jp][1],   QA[0][0], QA[0][1], QA[0][2], QA[0][3], b0, b1, z, z);
            MMA_F16(S[2*jp+1][0], S[2*jp+1][1], QA[0][0], QA[0][1], QA[0][2], QA[0][3], b2, b3, z, z);
            LDSM4(b0, b1, b2, b3, base + 32);
            MMA_F16(S[2*jp][0],   S[2*jp][1],   QA[1][0], QA[1][1], QA[1][2], QA[1][3], b0, b1, S[2*jp][0],   S[2*jp][1]);
            MMA_F16(S[2*jp+1][0], S[2*jp+1][1], QA[1][0], QA[1][1], QA[1][2], QA[1][3], b2, b3, S[2*jp+1][0], S[2*jp+1][1]);
        }
        #pragma unroll
        for (int j = 0; j < 16; j++) { H2EXP(S[j][0]); H2EXP(S[j][1]); }

        #pragma unroll
        for (int kk = 0; kk < 8; kk++) {
            uint32_t a0 = S[2*kk][0], a1 = S[2*kk][1], a2 = S[2*kk+1][0], a3 = S[2*kk+1][1];
            MMA_F32(Osum, a0, a1, a2, a3, bone, bone);
            #pragma unroll
            for (int nbp = 0; nbp < 2; nbp++) {
                uint32_t v0, v1, v2, v3;
                LDSM4(v0, v1, v2, v3, vb + nbp * 4352 + rowoff_v + kk * 32);
                MMA_F32(O[2*nbp],   a0, a1, a2, a3, v0, v1);
                MMA_F32(O[2*nbp+1], a0, a1, a2, a3, v2, v3);
            }
        }
        __syncthreads();
    }

    float rs0 = __shfl_sync(0xffffffffu, Osum[0], lane & ~3);
    float rs8 = __shfl_sync(0xffffffffu, Osum[2], lane & ~3);
    float inv0 = 1.f / rs0, inv8 = 1.f / rs8;
    float* Osm = reinterpret_cast<float*>(smem + FSMK0);  // [32 d][260]
    int row = lane >> 2;
    int qc = 16 * w + row;
    #pragma unroll
    for (int nb = 0; nb < 4; nb++) {
        int d0 = 8 * nb + 2 * (lane & 3);
        Osm[d0 * 260 + qc]           = O[nb][0] * inv0;
        Osm[(d0 + 1) * 260 + qc]     = O[nb][1] * inv0;
        Osm[d0 * 260 + qc + 8]       = O[nb][2] * inv8;
        Osm[(d0 + 1) * 260 + qc + 8] = O[nb][3] * inv8;
    }
    __syncthreads();
    __half* outp = aout + (size_t)(b * C_DIM + h * 32) * N_DIM + q0;
    for (int c = tid; c < 2048; c += 512) {
        int d = c >> 6, qq = (c & 63) * 4;
        float4 v = *reinterpret_cast<const float4*>(&Osm[d * 260 + qq]);
        uint2 pk;
        pk.x = packh(v.x, v.y); pk.y = packh(v.z, v.w);
        *reinterpret_cast<uint2*>(outp + (size_t)d * N_DIM + qq) = pk;
    }
}

// ---------------- launch ----------------
extern "C" void kernel_launch(void* const* d_in, const int* in_sizes, int n_in,
                              void* d_out, int out_size)
{
    const float* x    = (const float*)d_in[0];
    const float* gn_w = (const float*)d_in[1];
    const float* gn_b = (const float*)d_in[2];
    const float* wq   = (const float*)d_in[3];
    const float* bq   = (const float*)d_in[4];
    const float* wk   = (const float*)d_in[5];
    const float* bk   = (const float*)d_in[6];
    const float* wv   = (const float*)d_in[7];
    const float* bv   = (const float*)d_in[8];
    const float* wo   = (const float*)d_in[9];
    const float* bo   = (const float*)d_in[10];
    float* out = (float*)d_out;

    float *scl, *shf, *ps, *ps2;
    __half *wh, *xh, *qnd, *knd, *vdn, *attnh;
    cudaGetSymbolAddress((void**)&scl,   g_scale);
    cudaGetSymbolAddress((void**)&shf,   g_shift);
    cudaGetSymbolAddress((void**)&ps,    g_psum);
    cudaGetSymbolAddress((void**)&ps2,   g_psum2);
    cudaGetSymbolAddress((void**)&wh,    g_wh);
    cudaGetSymbolAddress((void**)&xh,    g_xh);
    cudaGetSymbolAddress((void**)&qnd,   g_qnd);
    cudaGetSymbolAddress((void**)&knd,   g_knd);
    cudaGetSymbolAddress((void**)&vdn,   g_vdn);
    cudaGetSymbolAddress((void**)&attnh, g_attnh);

    cudaFuncSetAttribute(flash_mma_kernel, cudaFuncAttributeMaxDynamicSharedMemorySize, FSM_TOTAL);

    gnA_kernel<<<192, 256>>>(x, wq, wk, wv, wo, ps, ps2, wh);
    gnB_kernel<<<1, 512>>>(ps, ps2, gn_w, gn_b, scl, shf);
    xconv_kernel<<<2048, 256>>>(x, scl, shf, xh);

    const float qs = 0.2550466864771404f;   // log2(e)/sqrt(32)
    dim3 qkvgrid(32, 6, 2);
    qkv_gemm_kernel<<<qkvgrid, 256>>>(wh, bq, bk, bv, xh, qnd, knd, vdn, qs);

    dim3 fgrid(16, HEADS, B_DIM);
    flash_mma_kernel<<<fgrid, 512, FSM_TOTAL>>>(qnd, knd, vdn, attnh);

    dim3 ogrid(32, 2, 2);
    oproj_kernel<<<ogrid, 256>>>(wh + 196608, bo, attnh, x, out);
}